// round 14
// baseline (speedup 1.0000x reference)
#include <cuda_runtime.h>
#include <cuda_bf16.h>
#include <math.h>
#include <stdint.h>

#define BB      2
#define NQ      5376
#define NVAL    5376
#define CDIM    256
#define HEADS   8
#define HD      32
#define LEVELS  3
#define POINTS  4
#define M_TOT   (BB * NQ)        // 10752
#define KDIM    256

// Scratch (device globals: no allocation allowed in kernel_launch)
__device__ float g_v[BB * NVAL * CDIM];        // projected value (fp32, gathered)
__device__ float g_off[BB * NQ * 192];         // sampling offsets
__device__ float g_a[BB * NQ * 96];            // attention logits
// bf16 hi/lo split operands
__device__ __nv_bfloat16 g_vh[BB * NVAL * CDIM],  g_vl[BB * NVAL * CDIM];
__device__ __nv_bfloat16 g_qh[BB * NQ * CDIM],    g_ql[BB * NQ * CDIM];
__device__ __nv_bfloat16 g_ath[BB * NQ * CDIM],   g_atl[BB * NQ * CDIM];
__device__ __nv_bfloat16 g_wvh[CDIM * CDIM],      g_wvl[CDIM * CDIM];
__device__ __nv_bfloat16 g_woffh[192 * CDIM],     g_woffl[192 * CDIM];
__device__ __nv_bfloat16 g_wah[96 * CDIM],        g_wal[96 * CDIM];
__device__ __nv_bfloat16 g_woh[CDIM * CDIM],      g_wol[CDIM * CDIM];

// ---------------------------------------------------------------------------
__device__ __forceinline__ uint32_t smem_u32(const void* p) {
    uint32_t a;
    asm("{ .reg .u64 t; cvta.to.shared.u64 t, %1; cvt.u32.u64 %0, t; }"
        : "=r"(a) : "l"(p));
    return a;
}

#define LDSM_X4(r0, r1, r2, r3, addr) \
    asm volatile("ldmatrix.sync.aligned.m8n8.x4.shared.b16 {%0,%1,%2,%3}, [%4];" \
        : "=r"(r0), "=r"(r1), "=r"(r2), "=r"(r3) : "r"(addr))

#define MMA_BF16(d, a, b) \
    asm volatile("mma.sync.aligned.m16n8k16.row.col.f32.bf16.bf16.f32 " \
        "{%0,%1,%2,%3}, {%4,%5,%6,%7}, {%8,%9}, {%0,%1,%2,%3};" \
        : "+f"((d)[0]), "+f"((d)[1]), "+f"((d)[2]), "+f"((d)[3]) \
        : "r"((a)[0]), "r"((a)[1]), "r"((a)[2]), "r"((a)[3]), \
          "r"((b)[0]), "r"((b)[1]))

__device__ __forceinline__ void cpa16(uint32_t dst, const void* src, int srcsz) {
    asm volatile("cp.async.ca.shared.global [%0], [%1], 16, %2;"
                 :: "r"(dst), "l"(src), "r"(srcsz) : "memory");
}

// split fp32 pair -> packed bf16x2 hi and lo
__device__ __forceinline__ void split2(float x, float y, uint32_t& hi, uint32_t& lo) {
    __nv_bfloat16 hx = __float2bfloat16(x);
    __nv_bfloat16 hy = __float2bfloat16(y);
    __nv_bfloat16 lx = __float2bfloat16(x - __bfloat162float(hx));
    __nv_bfloat16 ly = __float2bfloat16(y - __bfloat162float(hy));
    __nv_bfloat162 h; h.x = hx; h.y = hy;
    __nv_bfloat162 l; l.x = lx; l.y = ly;
    hi = *reinterpret_cast<uint32_t*>(&h);
    lo = *reinterpret_cast<uint32_t*>(&l);
}

// ---------------------------------------------------------------------------
// Elementwise fp32 -> (hi, lo) bf16 split.  n4 = element count / 4.
// ---------------------------------------------------------------------------
__global__ __launch_bounds__(256) void split_bf16(
    const float4* __restrict__ src, uint2* __restrict__ h, uint2* __restrict__ l, int n4)
{
    const int i = blockIdx.x * 256 + threadIdx.x;
    if (i < n4) {
        float4 v = src[i];
        uint2 hh, ll;
        split2(v.x, v.y, hh.x, ll.x);
        split2(v.z, v.w, hh.y, ll.y);
        h[i] = hh;
        l[i] = ll;
    }
}

// ---------------------------------------------------------------------------
// C = A @ W^T + bias via 3xBF16 split mma.sync, pre-split bf16 operands.
// Ah/Al: [M,256] bf16, Bh/Bl: [N,256] bf16, C: [M,N] fp32.
// BM=128, BN=128, BK=32. 8 warps: 2(m) x 4(n), warp tile 64x32.
// Double-buffered cp.async pipeline: 2 x 32KB smem (Ah,Al,Bh,Bl tiles).
// ---------------------------------------------------------------------------
__global__ __launch_bounds__(256, 2) void bf16_gemm(
    const __nv_bfloat16* __restrict__ Ah, const __nv_bfloat16* __restrict__ Al,
    const __nv_bfloat16* __restrict__ Bh, const __nv_bfloat16* __restrict__ Bl,
    const float* __restrict__ bias, float* __restrict__ C, int N)
{
    extern __shared__ __align__(128) char sm[];   // 2 x 32768
    const uint32_t sb = smem_u32(sm);

    const int tid  = threadIdx.x;
    const int lane = tid & 31;
    const int wid  = tid >> 5;
    const int wm   = wid & 1;
    const int wn   = wid >> 1;
    const int row0 = blockIdx.y * 128;
    const int col0 = blockIdx.x * 128;

    // cp.async loader mapping: 512 x 16B per tile; thread -> rows r4, r4+64, chunk ch
    const int r4 = tid >> 2;           // 0..63
    const int ch = tid & 3;            // 16B chunk within 64B row

    // within-tile ldmatrix offsets (k-step 0); step 1 = off ^ 32
    uint32_t aOff[4], bOff[2];
    {
        const int mlo = ((lane >> 3) & 1) * 8 + (lane & 7);
        const int ach = lane >> 4;
        #pragma unroll
        for (int i = 0; i < 4; i++) {
            const int m = wm * 64 + i * 16 + mlo;
            aOff[i] = m * 64 + ((ach ^ ((m >> 1) & 3)) << 4);
        }
        const int nlo = ((lane >> 4) & 1) * 8 + (lane & 7);
        const int bch = (lane >> 3) & 1;
        #pragma unroll
        for (int p = 0; p < 2; p++) {
            const int n = wn * 32 + p * 16 + nlo;
            bOff[p] = 16384 + n * 64 + ((bch ^ ((n >> 1) & 3)) << 4);
        }
    }

    float acc[4][4][4] = {};

    // ---- chunk loader (cp.async, swizzled dst) ----
    auto load_chunk = [&](int c, int buf) {
        const int kt = c * 32;
        const uint32_t bufb = sb + (buf << 15);
        #pragma unroll
        for (int i = 0; i < 2; i++) {
            const int row = r4 + 64 * i;
            const uint32_t dsw = (uint32_t)(row * 64 + ((ch ^ ((row >> 1) & 3)) << 4));
            const size_t aoff = (size_t)(row0 + row) * KDIM + kt + ch * 8;
            cpa16(bufb + dsw,         Ah + aoff, 16);
            cpa16(bufb + 8192 + dsw,  Al + aoff, 16);
            const int brow = col0 + row;
            const bool bv  = (brow < N);
            const size_t boff = (size_t)(bv ? brow : 0) * KDIM + kt + ch * 8;
            const int bs = bv ? 16 : 0;
            cpa16(bufb + 16384 + dsw, Bh + boff, bs);
            cpa16(bufb + 24576 + dsw, Bl + boff, bs);
        }
        asm volatile("cp.async.commit_group;" ::: "memory");
    };

    load_chunk(0, 0);

    for (int c = 0; c < KDIM / 32; c++) {
        if (c < KDIM / 32 - 1) {
            load_chunk(c + 1, (c + 1) & 1);
            asm volatile("cp.async.wait_group 1;" ::: "memory");
        } else {
            asm volatile("cp.async.wait_group 0;" ::: "memory");
        }
        __syncthreads();

        const uint32_t bufb = sb + ((c & 1) << 15);
        #pragma unroll
        for (int s = 0; s < 2; s++) {
            const uint32_t sx = s << 5;
            uint32_t ah[4][4], al[4][4];
            #pragma unroll
            for (int i = 0; i < 4; i++) {
                const uint32_t ad = bufb + (aOff[i] ^ sx);
                LDSM_X4(ah[i][0], ah[i][1], ah[i][2], ah[i][3], ad);
                LDSM_X4(al[i][0], al[i][1], al[i][2], al[i][3], ad + 8192);
            }
            #pragma unroll
            for (int p = 0; p < 2; p++) {
                uint32_t bh[4], bl[4];
                const uint32_t bd = bufb + (bOff[p] ^ sx);
                LDSM_X4(bh[0], bh[1], bh[2], bh[3], bd);
                LDSM_X4(bl[0], bl[1], bl[2], bl[3], bd + 8192);
                #pragma unroll
                for (int i = 0; i < 4; i++) {
                    #pragma unroll
                    for (int jj = 0; jj < 2; jj++) {
                        float* d = acc[i][p * 2 + jj];
                        MMA_BF16(d, ah[i], &bh[jj * 2]);
                        MMA_BF16(d, ah[i], &bl[jj * 2]);
                        MMA_BF16(d, al[i], &bh[jj * 2]);
                    }
                }
            }
        }
        __syncthreads();
    }

    // ---- epilogue: D frag -> C with bias ----
    #pragma unroll
    for (int i = 0; i < 4; i++) {
        const int r = row0 + wm * 64 + i * 16 + (lane >> 2);
        #pragma unroll
        for (int j = 0; j < 4; j++) {
            const int cc = col0 + wn * 32 + j * 8 + (lane & 3) * 2;
            if (cc < N) {
                const float b0 = __ldg(&bias[cc]);
                const float b1 = __ldg(&bias[cc + 1]);
                float2 o0 = make_float2(acc[i][j][0] + b0, acc[i][j][1] + b1);
                float2 o1 = make_float2(acc[i][j][2] + b0, acc[i][j][3] + b1);
                *reinterpret_cast<float2*>(&C[(size_t)r * N + cc])       = o0;
                *reinterpret_cast<float2*>(&C[(size_t)(r + 8) * N + cc]) = o1;
            }
        }
    }
}

// ---------------------------------------------------------------------------
// Sampling: one warp per (b, q, h). lane = channel d (HD=32).
// Output written directly as hi/lo bf16 split (feeds GEMM5).
// ---------------------------------------------------------------------------
__global__ __launch_bounds__(256) void msda_sample(const float* __restrict__ rp)
{
    const int w    = blockIdx.x * (blockDim.x >> 5) + (threadIdx.x >> 5);
    const int lane = threadIdx.x & 31;
    if (w >= BB * NQ * HEADS) return;

    const int h  = w & (HEADS - 1);
    const int bq = w >> 3;             // b*NQ + q
    const int b  = bq / NQ;

    // ---- softmax over 12 logits: lane j holds logit j ----
    const int  j   = lane;
    const bool act = (j < LEVELS * POINTS);
    float logit = act ? __ldg(&g_a[bq * 96 + h * 12 + j]) : -INFINITY;
    float mx = logit;
    #pragma unroll
    for (int s = 16; s; s >>= 1) mx = fmaxf(mx, __shfl_xor_sync(0xffffffffu, mx, s));
    float e = act ? __expf(logit - mx) : 0.f;
    float se = e;
    #pragma unroll
    for (int s = 16; s; s >>= 1) se += __shfl_xor_sync(0xffffffffu, se, s);
    const float aw = e / se;

    // ---- phase A: lanes 0..11 build the scalar package for point j ----
    const float rx = __ldg(&rp[bq * 2 + 0]);
    const float ry = __ldg(&rp[bq * 2 + 1]);

    int   I00 = 0, DXC = 0, DYC = 0;
    float w00 = 0.f, w01 = 0.f, w10 = 0.f, w11 = 0.f;
    {
        const int l  = j >> 2;
        const int Wl = 64 >> l;
        const int Hl = 64 >> l;
        const int st = (l == 0) ? 0 : ((l == 1) ? 4096 : 5120);

        float2 off = __ldg(reinterpret_cast<const float2*>(
            g_off + (size_t)bq * 192 + h * 24) + (act ? j : 0));

        float lx = fminf(fmaxf(rx + off.x, 0.f), 1.f);
        float ly = fminf(fmaxf(ry + off.y, 0.f), 1.f);
        float x = lx * (float)Wl - 0.5f;
        float y = ly * (float)Hl - 0.5f;
        float x0f = floorf(x), y0f = floorf(y);
        float wx = x - x0f,   wy = y - y0f;
        int x0 = (int)x0f, y0 = (int)y0f;

        int cx0 = max(x0, 0);
        int cy0 = max(y0, 0);
        int cx1 = min(x0 + 1, Wl - 1);
        int cy1 = min(y0 + 1, Hl - 1);
        float vx0 = (x0 >= 0)      ? 1.f : 0.f;
        float vx1 = (x0 + 1 < Wl)  ? 1.f : 0.f;
        float vy0 = (y0 >= 0)      ? 1.f : 0.f;
        float vy1 = (y0 + 1 < Hl)  ? 1.f : 0.f;

        float ax0 = (1.f - wx) * vx0, ax1 = wx * vx1;
        float ay0 = (1.f - wy) * vy0 * aw, ay1 = wy * vy1 * aw;
        w00 = ax0 * ay0; w01 = ax1 * ay0;
        w10 = ax0 * ay1; w11 = ax1 * ay1;

        I00 = (st + cy0 * Wl + cx0) * CDIM;
        DXC = (cx1 - cx0) * CDIM;
        DYC = (cy1 - cy0) * Wl * CDIM;
    }

    // ---- phase B: gather, lane = channel ----
    const float* vb = g_v + ((size_t)b * NVAL) * CDIM + h * HD + lane;
    float acc = 0.f;
    #pragma unroll
    for (int p = 0; p < LEVELS * POINTS; p++) {
        const int   I  = __shfl_sync(0xffffffffu, I00, p);
        const int   dx = __shfl_sync(0xffffffffu, DXC, p);
        const int   dy = __shfl_sync(0xffffffffu, DYC, p);
        const float a00 = __shfl_sync(0xffffffffu, w00, p);
        const float a01 = __shfl_sync(0xffffffffu, w01, p);
        const float a10 = __shfl_sync(0xffffffffu, w10, p);
        const float a11 = __shfl_sync(0xffffffffu, w11, p);
        const float* pt = vb + I;
        acc = fmaf(__ldg(pt),           a00, acc);
        acc = fmaf(__ldg(pt + dx),      a01, acc);
        acc = fmaf(__ldg(pt + dy),      a10, acc);
        acc = fmaf(__ldg(pt + dx + dy), a11, acc);
    }
    const size_t oidx = (size_t)bq * CDIM + h * HD + lane;
    const __nv_bfloat16 hi = __float2bfloat16(acc);
    g_ath[oidx] = hi;
    g_atl[oidx] = __float2bfloat16(acc - __bfloat162float(hi));
}

// ---------------------------------------------------------------------------
extern "C" void kernel_launch(void* const* d_in, const int* in_sizes, int n_in,
                              void* d_out, int out_size)
{
    const float* query = (const float*)d_in[0];
    const float* refp  = (const float*)d_in[1];
    const float* value = (const float*)d_in[2];
    const float* Wv    = (const float*)d_in[3];
    const float* bv    = (const float*)d_in[4];
    const float* Woff  = (const float*)d_in[5];
    const float* boff  = (const float*)d_in[6];
    const float* Wa    = (const float*)d_in[7];
    const float* ba    = (const float*)d_in[8];
    const float* Wo    = (const float*)d_in[9];
    const float* bo    = (const float*)d_in[10];
    float* out = (float*)d_out;

    float* pv;   cudaGetSymbolAddress((void**)&pv,   g_v);
    float* poff; cudaGetSymbolAddress((void**)&poff, g_off);
    float* pa;   cudaGetSymbolAddress((void**)&pa,   g_a);
    __nv_bfloat16 *pvh, *pvl, *pqh, *pql, *path, *patl;
    __nv_bfloat16 *pwvh, *pwvl, *pwoffh, *pwoffl, *pwah, *pwal, *pwoh, *pwol;
    cudaGetSymbolAddress((void**)&pvh,   g_vh);   cudaGetSymbolAddress((void**)&pvl,   g_vl);
    cudaGetSymbolAddress((void**)&pqh,   g_qh);   cudaGetSymbolAddress((void**)&pql,   g_ql);
    cudaGetSymbolAddress((void**)&path,  g_ath);  cudaGetSymbolAddress((void**)&patl,  g_atl);
    cudaGetSymbolAddress((void**)&pwvh,  g_wvh);  cudaGetSymbolAddress((void**)&pwvl,  g_wvl);
    cudaGetSymbolAddress((void**)&pwoffh,g_woffh);cudaGetSymbolAddress((void**)&pwoffl,g_woffl);
    cudaGetSymbolAddress((void**)&pwah,  g_wah);  cudaGetSymbolAddress((void**)&pwal,  g_wal);
    cudaGetSymbolAddress((void**)&pwoh,  g_woh);  cudaGetSymbolAddress((void**)&pwol,  g_wol);

    cudaFuncSetAttribute(bf16_gemm, cudaFuncAttributeMaxDynamicSharedMemorySize, 65536);

    auto split = [](const float* s, __nv_bfloat16* h, __nv_bfloat16* l, int n) {
        const int n4 = n / 4;
        split_bf16<<<(n4 + 255) / 256, 256>>>(
            (const float4*)s, (uint2*)h, (uint2*)l, n4);
    };

    // operand splits
    split(value, pvh, pvl, BB * NVAL * CDIM);
    split(query, pqh, pql, BB * NQ * CDIM);
    split(Wv,    pwvh,  pwvl,  CDIM * CDIM);
    split(Woff,  pwoffh,pwoffl,192 * CDIM);
    split(Wa,    pwah,  pwal,  96 * CDIM);
    split(Wo,    pwoh,  pwol,  CDIM * CDIM);

    const int mb = M_TOT / 128;   // 84

    // 1. v = value @ Wv^T + bv   (fp32 out for gather)
    bf16_gemm<<<dim3(2, mb), 256, 65536>>>(pvh, pvl, pwvh, pwvl, bv, pv, 256);
    // 2. off = query @ Woff^T + boff
    bf16_gemm<<<dim3(2, mb), 256, 65536>>>(pqh, pql, pwoffh, pwoffl, boff, poff, 192);
    // 3. a = query @ Wa^T + ba
    bf16_gemm<<<dim3(1, mb), 256, 65536>>>(pqh, pql, pwah, pwal, ba, pa, 96);
    // 4. sampling (one warp per (b,q,h)) -> bf16 hi/lo attn
    {
        int warps  = BB * NQ * HEADS;              // 86016
        int blocks = (warps + 7) / 8;
        msda_sample<<<blocks, 256>>>(refp);
    }
    // 5. out = attn @ Wo^T + bo
    bf16_gemm<<<dim3(2, mb), 256, 65536>>>(path, patl, pwoh, pwol, bo, out, 256);
}